// round 15
// baseline (speedup 1.0000x reference)
#include <cuda_runtime.h>
#include <cuda_fp16.h>
#include <math.h>
#include <stdint.h>

#define D_MODEL   2048
#define KV_DIM    512
#define HEAD_DIM  64
#define NUM_HEADS 32
#define BATCH     2
#define SEQ       2048
#define M_TOT     (BATCH*SEQ)   // 4096
#define K2        (2*D_MODEL)   // 4096 (2-pass split-K: A={hi,lo} x Bh)

// ---------------- scratch (__device__ globals; no allocation) ---------------
__device__ __half s_qih[(size_t)M_TOT * D_MODEL];
__device__ __half s_qil[(size_t)M_TOT * D_MODEL];
__device__ __half s_kih[(size_t)M_TOT * D_MODEL];
__device__ __half s_kil[(size_t)M_TOT * D_MODEL];
__device__ __half s_vih[(size_t)M_TOT * D_MODEL];
__device__ __half s_vil[(size_t)M_TOT * D_MODEL];
__device__ __half s_wqh[(size_t)D_MODEL * D_MODEL];
__device__ __half s_wkh[(size_t)D_MODEL * KV_DIM];
__device__ __half s_wvh[(size_t)D_MODEL * KV_DIM];
__device__ __half s_woh[(size_t)D_MODEL * D_MODEL];
__device__ __half g_Qh[(size_t)M_TOT * D_MODEL];           // pre-scaled, hi
__device__ __half g_Ql[(size_t)M_TOT * D_MODEL];           // pre-scaled, lo
__device__ __half g_KhT[(size_t)16 * HEAD_DIM * SEQ];      // [bg][d][t], hi only
__device__ __half g_Vh [(size_t)M_TOT * KV_DIM];           // hi only
__device__ __half g_AOh[(size_t)M_TOT * D_MODEL];
__device__ __half g_AOl[(size_t)M_TOT * D_MODEL];

// ------------------------------ helpers -------------------------------------
__device__ __forceinline__ uint32_t sptr(const void* p) {
    return (uint32_t)__cvta_generic_to_shared(p);
}
__device__ __forceinline__ void cp16(void* dst, const void* src) {
    asm volatile("cp.async.cg.shared.global [%0], [%1], 16;"
                 :: "r"(sptr(dst)), "l"(src));
}
__device__ __forceinline__ void cp_commit() { asm volatile("cp.async.commit_group;"); }
template<int N_> __device__ __forceinline__ void cp_wait() {
    asm volatile("cp.async.wait_group %0;" :: "n"(N_));
}
__device__ __forceinline__ void ldmA(uint32_t* r, uint32_t a) {
    asm volatile("ldmatrix.sync.aligned.m8n8.x4.shared.b16 {%0,%1,%2,%3}, [%4];"
                 : "=r"(r[0]), "=r"(r[1]), "=r"(r[2]), "=r"(r[3]) : "r"(a));
}
__device__ __forceinline__ void ldmBT(uint32_t* r, uint32_t a) {
    asm volatile("ldmatrix.sync.aligned.m8n8.x4.trans.shared.b16 {%0,%1,%2,%3}, [%4];"
                 : "=r"(r[0]), "=r"(r[1]), "=r"(r[2]), "=r"(r[3]) : "r"(a));
}
__device__ __forceinline__ void mma16816h(float* c, const uint32_t* a, const uint32_t* b) {
    asm volatile("mma.sync.aligned.m16n8k16.row.col.f32.f16.f16.f32 "
                 "{%0,%1,%2,%3}, {%4,%5,%6,%7}, {%8,%9}, {%0,%1,%2,%3};"
                 : "+f"(c[0]), "+f"(c[1]), "+f"(c[2]), "+f"(c[3])
                 : "r"(a[0]), "r"(a[1]), "r"(a[2]), "r"(a[3]), "r"(b[0]), "r"(b[1]));
}
__device__ __forceinline__ void split2h(float x, __half& hi, __half& lo) {
    hi = __float2half_rn(x);
    lo = __float2half_rn(x - __half2float(hi));
}
__device__ __forceinline__ __half2 mk2h(__half a, __half b) {
    __half2 r; r.x = a; r.y = b; return r;
}
__device__ __forceinline__ uint32_t packh(float a, float b) {
    __half2 t = __floats2half2_rn(a, b);
    return *reinterpret_cast<uint32_t*>(&t);
}

// ------------------------- conversion kernels -------------------------------
__global__ void split3_r15(const float* __restrict__ X0, const float* __restrict__ X1,
                           const float* __restrict__ X2,
                           __half* __restrict__ Y0h, __half* __restrict__ Y0l,
                           __half* __restrict__ Y1h, __half* __restrict__ Y1l,
                           __half* __restrict__ Y2h, __half* __restrict__ Y2l,
                           size_t n) {
    for (size_t i = (size_t)blockIdx.x * blockDim.x + threadIdx.x; i < n;
         i += (size_t)gridDim.x * blockDim.x) {
        __half h, l;
        split2h(X0[i], h, l); Y0h[i] = h; Y0l[i] = l;
        split2h(X1[i], h, l); Y1h[i] = h; Y1l[i] = l;
        split2h(X2[i], h, l); Y2h[i] = h; Y2l[i] = l;
    }
}
__global__ void tohalf4_r15(const float* __restrict__ W0, __half* __restrict__ Y0, size_t n0,
                            const float* __restrict__ W1, __half* __restrict__ Y1, size_t n1,
                            const float* __restrict__ W2, __half* __restrict__ Y2, size_t n2,
                            const float* __restrict__ W3, __half* __restrict__ Y3, size_t n3) {
    size_t total = n0 + n1 + n2 + n3;
    for (size_t i = (size_t)blockIdx.x * blockDim.x + threadIdx.x; i < total;
         i += (size_t)gridDim.x * blockDim.x) {
        if (i < n0)                Y0[i] = __float2half_rn(W0[i]);
        else if (i < n0 + n1)      Y1[i - n0] = __float2half_rn(W1[i - n0]);
        else if (i < n0 + n1 + n2) Y2[i - n0 - n1] = __float2half_rn(W2[i - n0 - n1]);
        else                       Y3[i - n0 - n1 - n2] = __float2half_rn(W3[i - n0 - n1 - n2]);
    }
}

// --------------------------- fp16 2-pass GEMM body --------------------------
// C = (Ah + Al)[M][K] * Bh[K][N] + bias; A segments {hi,lo} over logical K=2048.
// mode: 0 = f32 out; 1 = Q (*0.125, split hi/lo); 2 = V (hi only); 3 = K (hi, transpose)
#define GBM 128
#define GBN 128
#define GBK 32
#define ASTR 40
#define BSTR 136

__device__ __forceinline__ void gemm2_body(
    const __half* Ahi, const __half* Alo, const __half* Bh,
    const float* bias, __half* Chi, __half* Clo, float* Cf, int N, int mode,
    __half (*As)[GBM * ASTR], __half (*Bs)[GBK * BSTR],
    int rowBase, int colBase)
{
    const int tid = threadIdx.x, lane = tid & 31, wid = tid >> 5;
    const int wm = wid >> 2, wn = wid & 3;

    float acc[4][4][4];
#pragma unroll
    for (int a = 0; a < 4; a++)
#pragma unroll
        for (int b = 0; b < 4; b++)
#pragma unroll
            for (int c = 0; c < 4; c++) acc[a][b][c] = 0.f;

    auto loadTiles = [&](int s, int kt) {
        const int seg = kt >> 11, koff = kt & 2047;
        const __half* Ab = seg ? Alo : Ahi;
#pragma unroll
        for (int h = 0; h < 2; h++) {
            int c = tid + h * 256;
            cp16(&As[s][(c >> 2) * ASTR + (c & 3) * 8],
                 &Ab[(size_t)(rowBase + (c >> 2)) * D_MODEL + koff + (c & 3) * 8]);
        }
#pragma unroll
        for (int h = 0; h < 2; h++) {
            int c = tid + h * 256;
            cp16(&Bs[s][(c >> 4) * BSTR + (c & 15) * 8],
                 &Bh[(size_t)(koff + (c >> 4)) * N + colBase + (c & 15) * 8]);
        }
    };

    const int niter = K2 / GBK;      // 128
    loadTiles(0, 0); cp_commit();

    for (int t = 0; t < niter; t++) {
        const int cur = t & 1;
        cp_wait<0>();
        __syncthreads();
        if (t + 1 < niter) { loadTiles(1 - cur, (t + 1) * GBK); cp_commit(); }

        const __half* Ab = As[cur];
        const __half* Bb = Bs[cur];
#pragma unroll
        for (int kk = 0; kk < GBK; kk += 16) {
            uint32_t af[4][4], bf[2][4];
#pragma unroll
            for (int mi = 0; mi < 4; mi++)
                ldmA(af[mi], sptr(&Ab[(wm * 64 + mi * 16 + (lane & 15)) * ASTR
                                      + kk + 8 * (lane >> 4)]));
#pragma unroll
            for (int j = 0; j < 2; j++)
                ldmBT(bf[j], sptr(&Bb[(kk + (lane & 15)) * BSTR
                                      + wn * 32 + j * 16 + 8 * (lane >> 4)]));
#pragma unroll
            for (int mi = 0; mi < 4; mi++)
#pragma unroll
                for (int nj = 0; nj < 4; nj++)
                    mma16816h(acc[mi][nj], af[mi], &bf[nj >> 1][(nj & 1) * 2]);
        }
    }

#pragma unroll
    for (int mi = 0; mi < 4; mi++) {
        int row0 = rowBase + wm * 64 + mi * 16 + (lane >> 2);
#pragma unroll
        for (int nj = 0; nj < 4; nj++) {
            int col = colBase + wn * 32 + nj * 8 + 2 * (lane & 3);
            float bx = bias[col], by = bias[col + 1];
            float v00 = acc[mi][nj][0] + bx, v01 = acc[mi][nj][1] + by;
            float v10 = acc[mi][nj][2] + bx, v11 = acc[mi][nj][3] + by;
            if (mode == 0) {
                *reinterpret_cast<float2*>(Cf + (size_t)row0 * N + col) = make_float2(v00, v01);
                *reinterpret_cast<float2*>(Cf + (size_t)(row0 + 8) * N + col) = make_float2(v10, v11);
            } else if (mode == 1) {
                v00 *= 0.125f; v01 *= 0.125f; v10 *= 0.125f; v11 *= 0.125f;
                __half h00, l00, h01, l01, h10, l10, h11, l11;
                split2h(v00, h00, l00); split2h(v01, h01, l01);
                split2h(v10, h10, l10); split2h(v11, h11, l11);
                *reinterpret_cast<__half2*>(Chi + (size_t)row0 * N + col) = mk2h(h00, h01);
                *reinterpret_cast<__half2*>(Clo + (size_t)row0 * N + col) = mk2h(l00, l01);
                *reinterpret_cast<__half2*>(Chi + (size_t)(row0 + 8) * N + col) = mk2h(h10, h11);
                *reinterpret_cast<__half2*>(Clo + (size_t)(row0 + 8) * N + col) = mk2h(l10, l11);
            } else if (mode == 3) {
                int b = row0 >> 11, t = row0 & 2047;
                int g = col >> 6,  d = col & 63;
                size_t base0 = ((size_t)(b * 8 + g) * 64 + d) * SEQ;
                size_t base1 = base0 + SEQ;
                Chi[base0 + t]     = __float2half_rn(v00);
                Chi[base1 + t]     = __float2half_rn(v01);
                Chi[base0 + t + 8] = __float2half_rn(v10);
                Chi[base1 + t + 8] = __float2half_rn(v11);
            } else {
                *reinterpret_cast<__half2*>(Chi + (size_t)row0 * N + col) =
                    mk2h(__float2half_rn(v00), __float2half_rn(v01));
                *reinterpret_cast<__half2*>(Chi + (size_t)(row0 + 8) * N + col) =
                    mk2h(__float2half_rn(v10), __float2half_rn(v11));
            }
        }
    }
}

// unified Q+K+V projection: 768 CTAs, linearized blockIdx.x
// [0,512): Q (mode 1);  [512,640): K (mode 3);  [640,768): V (mode 2)
__global__ __launch_bounds__(256, 2) void proj_all_r15(
    const __half* __restrict__ qih, const __half* __restrict__ qil,
    const __half* __restrict__ wqh, const float* __restrict__ bq,
    __half* __restrict__ Qh, __half* __restrict__ Ql,
    const __half* __restrict__ kih, const __half* __restrict__ kil,
    const __half* __restrict__ wkh, const float* __restrict__ bk,
    __half* __restrict__ KhT,
    const __half* __restrict__ vih, const __half* __restrict__ vil,
    const __half* __restrict__ wvh, const float* __restrict__ bv,
    __half* __restrict__ Vh)
{
    __shared__ __half As[2][GBM * ASTR];
    __shared__ __half Bs[2][GBK * BSTR];
    const int bid = blockIdx.x;
    if (bid < 512) {
        gemm2_body(qih, qil, wqh, bq, Qh, Ql, nullptr, D_MODEL, 1, As, Bs,
                   (bid >> 4) * GBM, (bid & 15) * GBN);
    } else {
        const int b2 = bid - 512;
        const int z = b2 >> 7;
        const int r = (b2 & 127) >> 2, c = b2 & 3;
        if (z == 0)
            gemm2_body(kih, kil, wkh, bk, KhT, nullptr, nullptr, KV_DIM, 3, As, Bs,
                       r * GBM, c * GBN);
        else
            gemm2_body(vih, vil, wvh, bv, Vh, nullptr, nullptr, KV_DIM, 2, As, Bs,
                       r * GBM, c * GBN);
    }
}

// O projection
__global__ __launch_bounds__(256, 2) void gemm2_r15(
    const __half* __restrict__ Ahi, const __half* __restrict__ Alo,
    const __half* __restrict__ Bh,
    const float* __restrict__ bias, float* __restrict__ Cf, int N)
{
    __shared__ __half As[2][GBM * ASTR];
    __shared__ __half Bs[2][GBK * BSTR];
    gemm2_body(Ahi, Alo, Bh, bias, nullptr, nullptr, Cf, N, 0, As, Bs,
               blockIdx.y * GBM, blockIdx.x * GBN);
}

// ---------------- flash attention: EXACT R13 (2 heads / CTA, 2 CTA/SM) ------
#define FSTR 72

__global__ __launch_bounds__(256, 2) void gqa_flash_r15(
    const __half* __restrict__ Qh, const __half* __restrict__ Ql,
    const __half* __restrict__ KhT, const __half* __restrict__ Vh,
    __half* __restrict__ AOh, __half* __restrict__ AOl)
{
    extern __shared__ char smraw[];
    __half* Qhi = (__half*)smraw;                  // [128][FSTR]
    __half* Qlo = Qhi + 128 * FSTR;
    __half* Khs = Qlo + 128 * FSTR;                // [2][64][FSTR]
    __half* Vhs = Khs + 2 * 64 * FSTR;             // [2][64][FSTR]

    const int tid = threadIdx.x, lane = tid & 31, wid = tid >> 5;
    const int grp = lane >> 2, tq = lane & 3;
    const int qblk = blockIdx.x, hp = blockIdx.y, b = blockIdx.z;
    const int g = hp >> 1;
    const size_t bg = (size_t)(b * 8 + g);
    const int g64 = g * 64;

    auto loadKV = [&](int st, int jb) {
#pragma unroll
        for (int h = 0; h < 2; h++) {
            int c = tid + h * 256;
            int r = c >> 3, off8 = (c & 7) * 8;
            size_t ksrc = (bg * 64 + r) * (size_t)SEQ + jb * 64 + off8;
            size_t vsrc = ((size_t)(b * SEQ + jb * 64 + r)) * KV_DIM + g64 + off8;
            cp16(Khs + st * 64 * FSTR + r * FSTR + off8, KhT + ksrc);
            cp16(Vhs + st * 64 * FSTR + r * FSTR + off8, Vh + vsrc);
        }
    };

    loadKV(0, 0); cp_commit();
#pragma unroll
    for (int h = 0; h < 4; h++) {
        int c = tid + h * 256;
        int r = c >> 3, off8 = (c & 7) * 8;
        size_t src = ((size_t)(b * SEQ + qblk * 64 + (r & 63))) * D_MODEL
                   + (hp * 2 + (r >> 6)) * 64 + off8;
        cp16(Qhi + r * FSTR + off8, Qh + src);
        cp16(Qlo + r * FSTR + off8, Ql + src);
    }
    cp_commit();

    float m0 = -1e30f, m1 = -1e30f, l0 = 0.f, l1 = 0.f;
    float o[8][4];
#pragma unroll
    for (int i = 0; i < 8; i++)
#pragma unroll
        for (int j = 0; j < 4; j++) o[i][j] = 0.f;

    const uint32_t arow = (wid * 16 + (lane & 15)) * FSTR + 8 * (lane >> 4);
    const uint32_t brow = (lane & 15) * FSTR + 8 * (lane >> 4);

    for (int jb = 0; jb < SEQ / 64; jb++) {
        const int cur = jb & 1;
        cp_wait<0>();
        __syncthreads();
        if (jb + 1 < SEQ / 64) { loadKV(1 - cur, jb + 1); cp_commit(); }

        const __half* Kc = Khs + cur * 64 * FSTR;
        const __half* Vc = Vhs + cur * 64 * FSTR;

        // ---- S = (Qh + Ql) @ Kh^T (2-pass) ----
        float s[8][4];
#pragma unroll
        for (int i = 0; i < 8; i++)
#pragma unroll
            for (int j = 0; j < 4; j++) s[i][j] = 0.f;

#pragma unroll
        for (int p = 0; p < 2; p++) {
            const __half* Aseg = p ? Qlo : Qhi;
#pragma unroll
            for (int kk = 0; kk < 4; kk++) {
                uint32_t af[4], bf[4][4];
                ldmA(af, sptr(Aseg + kk * 16 + arow));
#pragma unroll
                for (int j = 0; j < 4; j++)
                    ldmBT(bf[j], sptr(Kc + kk * 16 * FSTR + j * 16 + brow));
#pragma unroll
                for (int nj = 0; nj < 8; nj++)
                    mma16816h(s[nj], af, &bf[nj >> 1][(nj & 1) * 2]);
            }
        }

        // ---- online softmax in registers ----
        float pm0 = -1e30f, pm1 = -1e30f;
#pragma unroll
        for (int nj = 0; nj < 8; nj++) {
            pm0 = fmaxf(pm0, fmaxf(s[nj][0], s[nj][1]));
            pm1 = fmaxf(pm1, fmaxf(s[nj][2], s[nj][3]));
        }
        pm0 = fmaxf(pm0, __shfl_xor_sync(~0u, pm0, 1));
        pm0 = fmaxf(pm0, __shfl_xor_sync(~0u, pm0, 2));
        pm1 = fmaxf(pm1, __shfl_xor_sync(~0u, pm1, 1));
        pm1 = fmaxf(pm1, __shfl_xor_sync(~0u, pm1, 2));
        float mn0 = fmaxf(m0, pm0), mn1 = fmaxf(m1, pm1);
        float corr0 = __expf(m0 - mn0), corr1 = __expf(m1 - mn1);
        m0 = mn0; m1 = mn1;

        float ls0 = 0.f, ls1 = 0.f;
        uint32_t pHi[4][4], pLo[4][4];
#pragma unroll
        for (int nj = 0; nj < 8; nj++) {
            float p0 = __expf(s[nj][0] - mn0);
            float p1 = __expf(s[nj][1] - mn0);
            float p2 = __expf(s[nj][2] - mn1);
            float p3 = __expf(s[nj][3] - mn1);
            ls0 += p0 + p1; ls1 += p2 + p3;
            const int kk = nj >> 1, hf = (nj & 1) * 2;
            uint32_t h01 = packh(p0, p1), h23 = packh(p2, p3);
            pHi[kk][hf]     = h01;
            pHi[kk][hf + 1] = h23;
            __half2 hh01 = *reinterpret_cast<__half2*>(&h01);
            __half2 hh23 = *reinterpret_cast<__half2*>(&h23);
            pLo[kk][hf]     = packh(p0 - __half2float(hh01.x),
                                    p1 - __half2float(hh01.y));
            pLo[kk][hf + 1] = packh(p2 - __half2float(hh23.x),
                                    p3 - __half2float(hh23.y));
        }
        ls0 += __shfl_xor_sync(~0u, ls0, 1); ls0 += __shfl_xor_sync(~0u, ls0, 2);
        ls1 += __shfl_xor_sync(~0u, ls1, 1); ls1 += __shfl_xor_sync(~0u, ls1, 2);
        l0 = l0 * corr0 + ls0;
        l1 = l1 * corr1 + ls1;
#pragma unroll
        for (int nj = 0; nj < 8; nj++) {
            o[nj][0] *= corr0; o[nj][1] *= corr0;
            o[nj][2] *= corr1; o[nj][3] *= corr1;
        }

        // ---- O += (Ph + Pl) @ Vh (2-pass, P in registers) ----
#pragma unroll
        for (int p = 0; p < 2; p++) {
            const uint32_t (*Pa)[4] = p ? pLo : pHi;
#pragma unroll
            for (int kk = 0; kk < 4; kk++) {
                uint32_t bf[4][4];
#pragma unroll
                for (int j = 0; j < 4; j++)
                    ldmBT(bf[j], sptr(Vc + kk * 16 * FSTR + j * 16 + brow));
#pragma unroll
                for (int nj = 0; nj < 8; nj++)
                    mma16816h(o[nj], Pa[kk], &bf[nj >> 1][(nj & 1) * 2]);
            }
        }
    }

    // ---- epilogue: normalize + split-write AO ----
    const int rowa = wid * 16 + grp;
    float il0 = 1.f / l0, il1 = 1.f / l1;
    int head = hp * 2 + (rowa >> 6);
    size_t m0r = (size_t)(b * SEQ + qblk * 64 + (rowa & 63));
#pragma unroll
    for (int nj = 0; nj < 8; nj++) {
        int col = head * 64 + nj * 8 + 2 * tq;
        float v00 = o[nj][0] * il0, v01 = o[nj][1] * il0;
        float v10 = o[nj][2] * il1, v11 = o[nj][3] * il1;
        __half h00, l00, h01, l01, h10, l10, h11, l11;
        split2h(v00, h00, l00); split2h(v01, h01, l01);
        split2h(v10, h10, l10); split2h(v11, h11, l11);
        *reinterpret_cast<__half2*>(AOh + m0r * D_MODEL + col) = mk2h(h00, h01);
        *reinterpret_cast<__half2*>(AOl + m0r * D_MODEL + col) = mk2h(l00, l01);
        *reinterpret_cast<__half2*>(AOh + (m0r + 8) * D_MODEL + col) = mk2h(h10, h11);
        *reinterpret_cast<__half2*>(AOl + (m0r + 8) * D_MODEL + col) = mk2h(l10, l11);
    }
}

// -----------------------------------------------------------------------------
extern "C" void kernel_launch(void* const* d_in, const int* in_sizes, int n_in,
                              void* d_out, int out_size)
{
    (void)in_sizes; (void)n_in; (void)out_size;
    const float* q  = (const float*)d_in[0];
    const float* k  = (const float*)d_in[1];
    const float* v  = (const float*)d_in[2];
    const float* Wq = (const float*)d_in[3];
    const float* bq = (const float*)d_in[4];
    const float* Wk = (const float*)d_in[5];
    const float* bk = (const float*)d_in[6];
    const float* Wv = (const float*)d_in[7];
    const float* bv = (const float*)d_in[8];
    const float* Wo = (const float*)d_in[9];
    const float* bo = (const float*)d_in[10];
    float* out = (float*)d_out;

    __half *qih,*qil,*kih,*kil,*vih,*vil;
    __half *wqh,*wkh,*wvh,*woh;
    __half *Qh,*Ql,*KhT,*Vh,*AOh,*AOl;
    cudaGetSymbolAddress((void**)&qih, s_qih); cudaGetSymbolAddress((void**)&qil, s_qil);
    cudaGetSymbolAddress((void**)&kih, s_kih); cudaGetSymbolAddress((void**)&kil, s_kil);
    cudaGetSymbolAddress((void**)&vih, s_vih); cudaGetSymbolAddress((void**)&vil, s_vil);
    cudaGetSymbolAddress((void**)&wqh, s_wqh); cudaGetSymbolAddress((void**)&wkh, s_wkh);
    cudaGetSymbolAddress((void**)&wvh, s_wvh); cudaGetSymbolAddress((void**)&woh, s_woh);
    cudaGetSymbolAddress((void**)&Qh,  g_Qh);  cudaGetSymbolAddress((void**)&Ql,  g_Ql);
    cudaGetSymbolAddress((void**)&KhT, g_KhT); cudaGetSymbolAddress((void**)&Vh,  g_Vh);
    cudaGetSymbolAddress((void**)&AOh, g_AOh); cudaGetSymbolAddress((void**)&AOl, g_AOl);

    const size_t flash_smem =
        (2 * 128 * FSTR + 2 * 2 * 64 * FSTR) * sizeof(__half);   // 73728
    cudaFuncSetAttribute(gqa_flash_r15, cudaFuncAttributeMaxDynamicSharedMemorySize,
                         (int)flash_smem);

    const size_t nMD = (size_t)M_TOT * D_MODEL;
    const size_t nDD = (size_t)D_MODEL * D_MODEL;
    const size_t nDK = (size_t)D_MODEL * KV_DIM;
    split3_r15<<<2048, 256>>>(q, k, v, qih, qil, kih, kil, vih, vil, nMD);
    tohalf4_r15<<<2048, 256>>>(Wq, wqh, nDD, Wk, wkh, nDK, Wv, wvh, nDK, Wo, woh, nDD);

    // unified Q+K+V projections (768 CTAs, one tail)
    proj_all_r15<<<768, 256>>>(
        qih, qil, wqh, bq, Qh, Ql,
        kih, kil, wkh, bk, KhT,
        vih, vil, wvh, bv, Vh);

    // attention (2 heads / CTA, 256 threads, 2 CTA/SM — validated R13 config)
    gqa_flash_r15<<<dim3(SEQ / 64, NUM_HEADS / 2, BATCH), 256, flash_smem>>>(
        Qh, Ql, KhT, Vh, AOh, AOl);

    // output projection
    gemm2_r15<<<dim3(D_MODEL / GBN, M_TOT / GBM), 256>>>(AOh, AOl, woh, bo, out, D_MODEL);
}

// round 16
// speedup vs baseline: 1.5116x; 1.5116x over previous
#include <cuda_runtime.h>
#include <cuda_fp16.h>
#include <math.h>
#include <stdint.h>

#define D_MODEL   2048
#define KV_DIM    512
#define HEAD_DIM  64
#define NUM_HEADS 32
#define BATCH     2
#define SEQ       2048
#define M_TOT     (BATCH*SEQ)   // 4096
#define K2        (2*D_MODEL)   // 4096 (2-pass split-K: A={hi,lo} x Bh)

// ---------------- scratch (__device__ globals; no allocation) ---------------
__device__ __half s_qih[(size_t)M_TOT * D_MODEL];
__device__ __half s_qil[(size_t)M_TOT * D_MODEL];
__device__ __half s_kih[(size_t)M_TOT * D_MODEL];
__device__ __half s_kil[(size_t)M_TOT * D_MODEL];
__device__ __half s_vih[(size_t)M_TOT * D_MODEL];
__device__ __half s_vil[(size_t)M_TOT * D_MODEL];
__device__ __half s_wqh[(size_t)D_MODEL * D_MODEL];
__device__ __half s_wkh[(size_t)D_MODEL * KV_DIM];
__device__ __half s_wvh[(size_t)D_MODEL * KV_DIM];
__device__ __half s_woh[(size_t)D_MODEL * D_MODEL];
__device__ __half g_Qh[(size_t)M_TOT * D_MODEL];           // pre-scaled, hi
__device__ __half g_Ql[(size_t)M_TOT * D_MODEL];           // pre-scaled, lo
__device__ __half g_KhT[(size_t)16 * HEAD_DIM * SEQ];      // [bg][d][t], hi only
__device__ __half g_Vh [(size_t)M_TOT * KV_DIM];           // hi only
__device__ __half g_AOh[(size_t)M_TOT * D_MODEL];
__device__ __half g_AOl[(size_t)M_TOT * D_MODEL];

// ------------------------------ helpers -------------------------------------
__device__ __forceinline__ uint32_t sptr(const void* p) {
    return (uint32_t)__cvta_generic_to_shared(p);
}
__device__ __forceinline__ void cp16(void* dst, const void* src) {
    asm volatile("cp.async.cg.shared.global [%0], [%1], 16;"
                 :: "r"(sptr(dst)), "l"(src));
}
__device__ __forceinline__ void cp_commit() { asm volatile("cp.async.commit_group;"); }
template<int N_> __device__ __forceinline__ void cp_wait() {
    asm volatile("cp.async.wait_group %0;" :: "n"(N_));
}
__device__ __forceinline__ void ldmA(uint32_t* r, uint32_t a) {
    asm volatile("ldmatrix.sync.aligned.m8n8.x4.shared.b16 {%0,%1,%2,%3}, [%4];"
                 : "=r"(r[0]), "=r"(r[1]), "=r"(r[2]), "=r"(r[3]) : "r"(a));
}
__device__ __forceinline__ void ldmBT(uint32_t* r, uint32_t a) {
    asm volatile("ldmatrix.sync.aligned.m8n8.x4.trans.shared.b16 {%0,%1,%2,%3}, [%4];"
                 : "=r"(r[0]), "=r"(r[1]), "=r"(r[2]), "=r"(r[3]) : "r"(a));
}
__device__ __forceinline__ void mma16816h(float* c, const uint32_t* a, const uint32_t* b) {
    asm volatile("mma.sync.aligned.m16n8k16.row.col.f32.f16.f16.f32 "
                 "{%0,%1,%2,%3}, {%4,%5,%6,%7}, {%8,%9}, {%0,%1,%2,%3};"
                 : "+f"(c[0]), "+f"(c[1]), "+f"(c[2]), "+f"(c[3])
                 : "r"(a[0]), "r"(a[1]), "r"(a[2]), "r"(a[3]), "r"(b[0]), "r"(b[1]));
}
__device__ __forceinline__ void split2h(float x, __half& hi, __half& lo) {
    hi = __float2half_rn(x);
    lo = __float2half_rn(x - __half2float(hi));
}
__device__ __forceinline__ __half2 mk2h(__half a, __half b) {
    __half2 r; r.x = a; r.y = b; return r;
}
__device__ __forceinline__ uint32_t packh(float a, float b) {
    __half2 t = __floats2half2_rn(a, b);
    return *reinterpret_cast<uint32_t*>(&t);
}

// ------------------------- fused prep kernel --------------------------------
// One launch: activation splits (q,k,v -> hi/lo) + weight casts (4 tensors).
// Index space: [0, nMD) activations (3 tensors each), then weights appended.
__global__ void prep_all_r16(
    const float* __restrict__ q, const float* __restrict__ k, const float* __restrict__ v,
    __half* __restrict__ qih, __half* __restrict__ qil,
    __half* __restrict__ kih, __half* __restrict__ kil,
    __half* __restrict__ vih, __half* __restrict__ vil, size_t nMD,
    const float* __restrict__ Wq, __half* __restrict__ wqh, size_t nDD,
    const float* __restrict__ Wk, __half* __restrict__ wkh, size_t nDK,
    const float* __restrict__ Wv, __half* __restrict__ wvh,
    const float* __restrict__ Wo, __half* __restrict__ woh)
{
    const size_t total = nMD + 2 * nDD + 2 * nDK;
    for (size_t i = (size_t)blockIdx.x * blockDim.x + threadIdx.x; i < total;
         i += (size_t)gridDim.x * blockDim.x) {
        if (i < nMD) {
            __half h, l;
            split2h(q[i], h, l); qih[i] = h; qil[i] = l;
            split2h(k[i], h, l); kih[i] = h; kil[i] = l;
            split2h(v[i], h, l); vih[i] = h; vil[i] = l;
        } else {
            size_t j = i - nMD;
            if (j < nDD)                 wqh[j] = __float2half_rn(Wq[j]);
            else if (j < nDD + nDK)      wkh[j - nDD] = __float2half_rn(Wk[j - nDD]);
            else if (j < nDD + 2 * nDK)  wvh[j - nDD - nDK] = __float2half_rn(Wv[j - nDD - nDK]);
            else                         woh[j - nDD - 2 * nDK] = __float2half_rn(Wo[j - nDD - 2 * nDK]);
        }
    }
}

// --------------------------- fp16 2-pass GEMM body --------------------------
// C = (Ah + Al)[M][K] * Bh[K][N] + bias; A segments {hi,lo} over logical K=2048.
// mode: 0 = f32 out; 1 = Q (*0.125, split hi/lo); 2 = V (hi only); 3 = K (hi, transpose)
#define GBM 128
#define GBN 128
#define GBK 32
#define ASTR 40
#define BSTR 136

__device__ __forceinline__ void gemm2_body(
    const __half* Ahi, const __half* Alo, const __half* Bh,
    const float* bias, __half* Chi, __half* Clo, float* Cf, int N, int mode,
    __half (*As)[GBM * ASTR], __half (*Bs)[GBK * BSTR],
    int rowBase, int colBase)
{
    const int tid = threadIdx.x, lane = tid & 31, wid = tid >> 5;
    const int wm = wid >> 2, wn = wid & 3;

    float acc[4][4][4];
#pragma unroll
    for (int a = 0; a < 4; a++)
#pragma unroll
        for (int b = 0; b < 4; b++)
#pragma unroll
            for (int c = 0; c < 4; c++) acc[a][b][c] = 0.f;

    auto loadTiles = [&](int s, int kt) {
        const int seg = kt >> 11, koff = kt & 2047;
        const __half* Ab = seg ? Alo : Ahi;
#pragma unroll
        for (int h = 0; h < 2; h++) {
            int c = tid + h * 256;
            cp16(&As[s][(c >> 2) * ASTR + (c & 3) * 8],
                 &Ab[(size_t)(rowBase + (c >> 2)) * D_MODEL + koff + (c & 3) * 8]);
        }
#pragma unroll
        for (int h = 0; h < 2; h++) {
            int c = tid + h * 256;
            cp16(&Bs[s][(c >> 4) * BSTR + (c & 15) * 8],
                 &Bh[(size_t)(koff + (c >> 4)) * N + colBase + (c & 15) * 8]);
        }
    };

    const int niter = K2 / GBK;      // 128
    loadTiles(0, 0); cp_commit();

    for (int t = 0; t < niter; t++) {
        const int cur = t & 1;
        cp_wait<0>();
        __syncthreads();
        if (t + 1 < niter) { loadTiles(1 - cur, (t + 1) * GBK); cp_commit(); }

        const __half* Ab = As[cur];
        const __half* Bb = Bs[cur];
#pragma unroll
        for (int kk = 0; kk < GBK; kk += 16) {
            uint32_t af[4][4], bf[2][4];
#pragma unroll
            for (int mi = 0; mi < 4; mi++)
                ldmA(af[mi], sptr(&Ab[(wm * 64 + mi * 16 + (lane & 15)) * ASTR
                                      + kk + 8 * (lane >> 4)]));
#pragma unroll
            for (int j = 0; j < 2; j++)
                ldmBT(bf[j], sptr(&Bb[(kk + (lane & 15)) * BSTR
                                      + wn * 32 + j * 16 + 8 * (lane >> 4)]));
#pragma unroll
            for (int mi = 0; mi < 4; mi++)
#pragma unroll
                for (int nj = 0; nj < 4; nj++)
                    mma16816h(acc[mi][nj], af[mi], &bf[nj >> 1][(nj & 1) * 2]);
        }
    }

#pragma unroll
    for (int mi = 0; mi < 4; mi++) {
        int row0 = rowBase + wm * 64 + mi * 16 + (lane >> 2);
#pragma unroll
        for (int nj = 0; nj < 4; nj++) {
            int col = colBase + wn * 32 + nj * 8 + 2 * (lane & 3);
            float bx = bias[col], by = bias[col + 1];
            float v00 = acc[mi][nj][0] + bx, v01 = acc[mi][nj][1] + by;
            float v10 = acc[mi][nj][2] + bx, v11 = acc[mi][nj][3] + by;
            if (mode == 0) {
                *reinterpret_cast<float2*>(Cf + (size_t)row0 * N + col) = make_float2(v00, v01);
                *reinterpret_cast<float2*>(Cf + (size_t)(row0 + 8) * N + col) = make_float2(v10, v11);
            } else if (mode == 1) {
                v00 *= 0.125f; v01 *= 0.125f; v10 *= 0.125f; v11 *= 0.125f;
                __half h00, l00, h01, l01, h10, l10, h11, l11;
                split2h(v00, h00, l00); split2h(v01, h01, l01);
                split2h(v10, h10, l10); split2h(v11, h11, l11);
                *reinterpret_cast<__half2*>(Chi + (size_t)row0 * N + col) = mk2h(h00, h01);
                *reinterpret_cast<__half2*>(Clo + (size_t)row0 * N + col) = mk2h(l00, l01);
                *reinterpret_cast<__half2*>(Chi + (size_t)(row0 + 8) * N + col) = mk2h(h10, h11);
                *reinterpret_cast<__half2*>(Clo + (size_t)(row0 + 8) * N + col) = mk2h(l10, l11);
            } else if (mode == 3) {
                int b = row0 >> 11, t = row0 & 2047;
                int g = col >> 6,  d = col & 63;
                size_t base0 = ((size_t)(b * 8 + g) * 64 + d) * SEQ;
                size_t base1 = base0 + SEQ;
                Chi[base0 + t]     = __float2half_rn(v00);
                Chi[base1 + t]     = __float2half_rn(v01);
                Chi[base0 + t + 8] = __float2half_rn(v10);
                Chi[base1 + t + 8] = __float2half_rn(v11);
            } else {
                *reinterpret_cast<__half2*>(Chi + (size_t)row0 * N + col) =
                    mk2h(__float2half_rn(v00), __float2half_rn(v01));
                *reinterpret_cast<__half2*>(Chi + (size_t)(row0 + 8) * N + col) =
                    mk2h(__float2half_rn(v10), __float2half_rn(v11));
            }
        }
    }
}

// unified Q+K+V projection: 768 CTAs, linearized blockIdx.x
// [0,512): Q (mode 1);  [512,640): K (mode 3);  [640,768): V (mode 2)
__global__ __launch_bounds__(256, 2) void proj_all_r16(
    const __half* __restrict__ qih, const __half* __restrict__ qil,
    const __half* __restrict__ wqh, const float* __restrict__ bq,
    __half* __restrict__ Qh, __half* __restrict__ Ql,
    const __half* __restrict__ kih, const __half* __restrict__ kil,
    const __half* __restrict__ wkh, const float* __restrict__ bk,
    __half* __restrict__ KhT,
    const __half* __restrict__ vih, const __half* __restrict__ vil,
    const __half* __restrict__ wvh, const float* __restrict__ bv,
    __half* __restrict__ Vh)
{
    __shared__ __half As[2][GBM * ASTR];
    __shared__ __half Bs[2][GBK * BSTR];
    const int bid = blockIdx.x;
    if (bid < 512) {
        gemm2_body(qih, qil, wqh, bq, Qh, Ql, nullptr, D_MODEL, 1, As, Bs,
                   (bid >> 4) * GBM, (bid & 15) * GBN);
    } else {
        const int b2 = bid - 512;
        const int z = b2 >> 7;
        const int r = (b2 & 127) >> 2, c = b2 & 3;
        if (z == 0)
            gemm2_body(kih, kil, wkh, bk, KhT, nullptr, nullptr, KV_DIM, 3, As, Bs,
                       r * GBM, c * GBN);
        else
            gemm2_body(vih, vil, wvh, bv, Vh, nullptr, nullptr, KV_DIM, 2, As, Bs,
                       r * GBM, c * GBN);
    }
}

// O projection
__global__ __launch_bounds__(256, 2) void gemm2_r16(
    const __half* __restrict__ Ahi, const __half* __restrict__ Alo,
    const __half* __restrict__ Bh,
    const float* __restrict__ bias, float* __restrict__ Cf, int N)
{
    __shared__ __half As[2][GBM * ASTR];
    __shared__ __half Bs[2][GBK * BSTR];
    gemm2_body(Ahi, Alo, Bh, bias, nullptr, nullptr, Cf, N, 0, As, Bs,
               blockIdx.y * GBM, blockIdx.x * GBN);
}

// ---------------- flash attention (validated: 2 heads / CTA, 2 CTA/SM) ------
#define FSTR 72

__global__ __launch_bounds__(256, 2) void gqa_flash_r16(
    const __half* __restrict__ Qh, const __half* __restrict__ Ql,
    const __half* __restrict__ KhT, const __half* __restrict__ Vh,
    __half* __restrict__ AOh, __half* __restrict__ AOl)
{
    extern __shared__ char smraw[];
    __half* Qhi = (__half*)smraw;                  // [128][FSTR]
    __half* Qlo = Qhi + 128 * FSTR;
    __half* Khs = Qlo + 128 * FSTR;                // [2][64][FSTR]
    __half* Vhs = Khs + 2 * 64 * FSTR;             // [2][64][FSTR]

    const int tid = threadIdx.x, lane = tid & 31, wid = tid >> 5;
    const int grp = lane >> 2, tq = lane & 3;
    const int qblk = blockIdx.x, hp = blockIdx.y, b = blockIdx.z;
    const int g = hp >> 1;
    const size_t bg = (size_t)(b * 8 + g);
    const int g64 = g * 64;

    auto loadKV = [&](int st, int jb) {
#pragma unroll
        for (int h = 0; h < 2; h++) {
            int c = tid + h * 256;
            int r = c >> 3, off8 = (c & 7) * 8;
            size_t ksrc = (bg * 64 + r) * (size_t)SEQ + jb * 64 + off8;
            size_t vsrc = ((size_t)(b * SEQ + jb * 64 + r)) * KV_DIM + g64 + off8;
            cp16(Khs + st * 64 * FSTR + r * FSTR + off8, KhT + ksrc);
            cp16(Vhs + st * 64 * FSTR + r * FSTR + off8, Vh + vsrc);
        }
    };

    loadKV(0, 0); cp_commit();
#pragma unroll
    for (int h = 0; h < 4; h++) {
        int c = tid + h * 256;
        int r = c >> 3, off8 = (c & 7) * 8;
        size_t src = ((size_t)(b * SEQ + qblk * 64 + (r & 63))) * D_MODEL
                   + (hp * 2 + (r >> 6)) * 64 + off8;
        cp16(Qhi + r * FSTR + off8, Qh + src);
        cp16(Qlo + r * FSTR + off8, Ql + src);
    }
    cp_commit();

    float m0 = -1e30f, m1 = -1e30f, l0 = 0.f, l1 = 0.f;
    float o[8][4];
#pragma unroll
    for (int i = 0; i < 8; i++)
#pragma unroll
        for (int j = 0; j < 4; j++) o[i][j] = 0.f;

    const uint32_t arow = (wid * 16 + (lane & 15)) * FSTR + 8 * (lane >> 4);
    const uint32_t brow = (lane & 15) * FSTR + 8 * (lane >> 4);

    for (int jb = 0; jb < SEQ / 64; jb++) {
        const int cur = jb & 1;
        cp_wait<0>();
        __syncthreads();
        if (jb + 1 < SEQ / 64) { loadKV(1 - cur, jb + 1); cp_commit(); }

        const __half* Kc = Khs + cur * 64 * FSTR;
        const __half* Vc = Vhs + cur * 64 * FSTR;

        // ---- S = (Qh + Ql) @ Kh^T (2-pass) ----
        float s[8][4];
#pragma unroll
        for (int i = 0; i < 8; i++)
#pragma unroll
            for (int j = 0; j < 4; j++) s[i][j] = 0.f;

#pragma unroll
        for (int p = 0; p < 2; p++) {
            const __half* Aseg = p ? Qlo : Qhi;
#pragma unroll
            for (int kk = 0; kk < 4; kk++) {
                uint32_t af[4], bf[4][4];
                ldmA(af, sptr(Aseg + kk * 16 + arow));
#pragma unroll
                for (int j = 0; j < 4; j++)
                    ldmBT(bf[j], sptr(Kc + kk * 16 * FSTR + j * 16 + brow));
#pragma unroll
                for (int nj = 0; nj < 8; nj++)
                    mma16816h(s[nj], af, &bf[nj >> 1][(nj & 1) * 2]);
            }
        }

        // ---- online softmax in registers ----
        float pm0 = -1e30f, pm1 = -1e30f;
#pragma unroll
        for (int nj = 0; nj < 8; nj++) {
            pm0 = fmaxf(pm0, fmaxf(s[nj][0], s[nj][1]));
            pm1 = fmaxf(pm1, fmaxf(s[nj][2], s[nj][3]));
        }
        pm0 = fmaxf(pm0, __shfl_xor_sync(~0u, pm0, 1));
        pm0 = fmaxf(pm0, __shfl_xor_sync(~0u, pm0, 2));
        pm1 = fmaxf(pm1, __shfl_xor_sync(~0u, pm1, 1));
        pm1 = fmaxf(pm1, __shfl_xor_sync(~0u, pm1, 2));
        float mn0 = fmaxf(m0, pm0), mn1 = fmaxf(m1, pm1);
        float corr0 = __expf(m0 - mn0), corr1 = __expf(m1 - mn1);
        m0 = mn0; m1 = mn1;

        float ls0 = 0.f, ls1 = 0.f;
        uint32_t pHi[4][4], pLo[4][4];
#pragma unroll
        for (int nj = 0; nj < 8; nj++) {
            float p0 = __expf(s[nj][0] - mn0);
            float p1 = __expf(s[nj][1] - mn0);
            float p2 = __expf(s[nj][2] - mn1);
            float p3 = __expf(s[nj][3] - mn1);
            ls0 += p0 + p1; ls1 += p2 + p3;
            const int kk = nj >> 1, hf = (nj & 1) * 2;
            uint32_t h01 = packh(p0, p1), h23 = packh(p2, p3);
            pHi[kk][hf]     = h01;
            pHi[kk][hf + 1] = h23;
            __half2 hh01 = *reinterpret_cast<__half2*>(&h01);
            __half2 hh23 = *reinterpret_cast<__half2*>(&h23);
            pLo[kk][hf]     = packh(p0 - __half2float(hh01.x),
                                    p1 - __half2float(hh01.y));
            pLo[kk][hf + 1] = packh(p2 - __half2float(hh23.x),
                                    p3 - __half2float(hh23.y));
        }
        ls0 += __shfl_xor_sync(~0u, ls0, 1); ls0 += __shfl_xor_sync(~0u, ls0, 2);
        ls1 += __shfl_xor_sync(~0u, ls1, 1); ls1 += __shfl_xor_sync(~0u, ls1, 2);
        l0 = l0 * corr0 + ls0;
        l1 = l1 * corr1 + ls1;
#pragma unroll
        for (int nj = 0; nj < 8; nj++) {
            o[nj][0] *= corr0; o[nj][1] *= corr0;
            o[nj][2] *= corr1; o[nj][3] *= corr1;
        }

        // ---- O += (Ph + Pl) @ Vh (2-pass, P in registers) ----
#pragma unroll
        for (int p = 0; p < 2; p++) {
            const uint32_t (*Pa)[4] = p ? pLo : pHi;
#pragma unroll
            for (int kk = 0; kk < 4; kk++) {
                uint32_t bf[4][4];
#pragma unroll
                for (int j = 0; j < 4; j++)
                    ldmBT(bf[j], sptr(Vc + kk * 16 * FSTR + j * 16 + brow));
#pragma unroll
                for (int nj = 0; nj < 8; nj++)
                    mma16816h(o[nj], Pa[kk], &bf[nj >> 1][(nj & 1) * 2]);
            }
        }
    }

    // ---- epilogue: normalize + split-write AO ----
    const int rowa = wid * 16 + grp;
    float il0 = 1.f / l0, il1 = 1.f / l1;
    int head = hp * 2 + (rowa >> 6);
    size_t m0r = (size_t)(b * SEQ + qblk * 64 + (rowa & 63));
#pragma unroll
    for (int nj = 0; nj < 8; nj++) {
        int col = head * 64 + nj * 8 + 2 * tq;
        float v00 = o[nj][0] * il0, v01 = o[nj][1] * il0;
        float v10 = o[nj][2] * il1, v11 = o[nj][3] * il1;
        __half h00, l00, h01, l01, h10, l10, h11, l11;
        split2h(v00, h00, l00); split2h(v01, h01, l01);
        split2h(v10, h10, l10); split2h(v11, h11, l11);
        *reinterpret_cast<__half2*>(AOh + m0r * D_MODEL + col) = mk2h(h00, h01);
        *reinterpret_cast<__half2*>(AOl + m0r * D_MODEL + col) = mk2h(l00, l01);
        *reinterpret_cast<__half2*>(AOh + (m0r + 8) * D_MODEL + col) = mk2h(h10, h11);
        *reinterpret_cast<__half2*>(AOl + (m0r + 8) * D_MODEL + col) = mk2h(l10, l11);
    }
}

// -----------------------------------------------------------------------------
extern "C" void kernel_launch(void* const* d_in, const int* in_sizes, int n_in,
                              void* d_out, int out_size)
{
    (void)in_sizes; (void)n_in; (void)out_size;
    const float* q  = (const float*)d_in[0];
    const float* k  = (const float*)d_in[1];
    const float* v  = (const float*)d_in[2];
    const float* Wq = (const float*)d_in[3];
    const float* bq = (const float*)d_in[4];
    const float* Wk = (const float*)d_in[5];
    const float* bk = (const float*)d_in[6];
    const float* Wv = (const float*)d_in[7];
    const float* bv = (const float*)d_in[8];
    const float* Wo = (const float*)d_in[9];
    const float* bo = (const float*)d_in[10];
    float* out = (float*)d_out;

    __half *qih,*qil,*kih,*kil,*vih,*vil;
    __half *wqh,*wkh,*wvh,*woh;
    __half *Qh,*Ql,*KhT,*Vh,*AOh,*AOl;
    cudaGetSymbolAddress((void**)&qih, s_qih); cudaGetSymbolAddress((void**)&qil, s_qil);
    cudaGetSymbolAddress((void**)&kih, s_kih); cudaGetSymbolAddress((void**)&kil, s_kil);
    cudaGetSymbolAddress((void**)&vih, s_vih); cudaGetSymbolAddress((void**)&vil, s_vil);
    cudaGetSymbolAddress((void**)&wqh, s_wqh); cudaGetSymbolAddress((void**)&wkh, s_wkh);
    cudaGetSymbolAddress((void**)&wvh, s_wvh); cudaGetSymbolAddress((void**)&woh, s_woh);
    cudaGetSymbolAddress((void**)&Qh,  g_Qh);  cudaGetSymbolAddress((void**)&Ql,  g_Ql);
    cudaGetSymbolAddress((void**)&KhT, g_KhT); cudaGetSymbolAddress((void**)&Vh,  g_Vh);
    cudaGetSymbolAddress((void**)&AOh, g_AOh); cudaGetSymbolAddress((void**)&AOl, g_AOl);

    const size_t flash_smem =
        (2 * 128 * FSTR + 2 * 2 * 64 * FSTR) * sizeof(__half);   // 73728
    cudaFuncSetAttribute(gqa_flash_r16, cudaFuncAttributeMaxDynamicSharedMemorySize,
                         (int)flash_smem);

    const size_t nMD = (size_t)M_TOT * D_MODEL;
    const size_t nDD = (size_t)D_MODEL * D_MODEL;
    const size_t nDK = (size_t)D_MODEL * KV_DIM;

    // fused prep: one launch for all splits + casts
    prep_all_r16<<<2048, 256>>>(q, k, v, qih, qil, kih, kil, vih, vil, nMD,
                                Wq, wqh, nDD, Wk, wkh, nDK, Wv, wvh, Wo, woh);

    // unified Q+K+V projections (768 CTAs, one tail)
    proj_all_r16<<<768, 256>>>(
        qih, qil, wqh, bq, Qh, Ql,
        kih, kil, wkh, bk, KhT,
        vih, vil, wvh, bv, Vh);

    // attention (2 heads / CTA, 256 threads, 2 CTA/SM — validated config)
    gqa_flash_r16<<<dim3(SEQ / 64, NUM_HEADS / 2, BATCH), 256, flash_smem>>>(
        Qh, Ql, KhT, Vh, AOh, AOl);

    // output projection
    gemm2_r16<<<dim3(D_MODEL / GBN, M_TOT / GBM), 256>>>(AOh, AOl, woh, bo, out, D_MODEL);
}

// round 17
// speedup vs baseline: 1.5365x; 1.0165x over previous
#include <cuda_runtime.h>
#include <cuda_fp16.h>
#include <math.h>
#include <stdint.h>

#define D_MODEL   2048
#define KV_DIM    512
#define HEAD_DIM  64
#define NUM_HEADS 32
#define BATCH     2
#define SEQ       2048
#define M_TOT     (BATCH*SEQ)   // 4096
#define K2        (2*D_MODEL)   // 4096 (2-pass split-K: A={hi,lo} x Bh)

// ---------------- scratch (__device__ globals; no allocation) ---------------
__device__ __half s_qih[(size_t)M_TOT * D_MODEL];
__device__ __half s_qil[(size_t)M_TOT * D_MODEL];
__device__ __half s_kih[(size_t)M_TOT * D_MODEL];
__device__ __half s_kil[(size_t)M_TOT * D_MODEL];
__device__ __half s_vih[(size_t)M_TOT * D_MODEL];
__device__ __half s_vil[(size_t)M_TOT * D_MODEL];
__device__ __half s_wqh[(size_t)D_MODEL * D_MODEL];
__device__ __half s_wkh[(size_t)D_MODEL * KV_DIM];
__device__ __half s_wvh[(size_t)D_MODEL * KV_DIM];
__device__ __half s_woh[(size_t)D_MODEL * D_MODEL];
__device__ __half g_Qh[(size_t)M_TOT * D_MODEL];           // pre-scaled, hi
__device__ __half g_Ql[(size_t)M_TOT * D_MODEL];           // pre-scaled, lo
__device__ __half g_KhT[(size_t)16 * HEAD_DIM * SEQ];      // [bg][d][t], hi only
__device__ __half g_Vh [(size_t)M_TOT * KV_DIM];           // hi only
__device__ __half g_AOh[(size_t)M_TOT * D_MODEL];
__device__ __half g_AOl[(size_t)M_TOT * D_MODEL];

// ------------------------------ helpers -------------------------------------
__device__ __forceinline__ uint32_t sptr(const void* p) {
    return (uint32_t)__cvta_generic_to_shared(p);
}
__device__ __forceinline__ void cp16(void* dst, const void* src) {
    asm volatile("cp.async.cg.shared.global [%0], [%1], 16;"
                 :: "r"(sptr(dst)), "l"(src));
}
__device__ __forceinline__ void cp_commit() { asm volatile("cp.async.commit_group;"); }
template<int N_> __device__ __forceinline__ void cp_wait() {
    asm volatile("cp.async.wait_group %0;" :: "n"(N_));
}
__device__ __forceinline__ void ldmA(uint32_t* r, uint32_t a) {
    asm volatile("ldmatrix.sync.aligned.m8n8.x4.shared.b16 {%0,%1,%2,%3}, [%4];"
                 : "=r"(r[0]), "=r"(r[1]), "=r"(r[2]), "=r"(r[3]) : "r"(a));
}
__device__ __forceinline__ void ldmBT(uint32_t* r, uint32_t a) {
    asm volatile("ldmatrix.sync.aligned.m8n8.x4.trans.shared.b16 {%0,%1,%2,%3}, [%4];"
                 : "=r"(r[0]), "=r"(r[1]), "=r"(r[2]), "=r"(r[3]) : "r"(a));
}
__device__ __forceinline__ void mma16816h(float* c, const uint32_t* a, const uint32_t* b) {
    asm volatile("mma.sync.aligned.m16n8k16.row.col.f32.f16.f16.f32 "
                 "{%0,%1,%2,%3}, {%4,%5,%6,%7}, {%8,%9}, {%0,%1,%2,%3};"
                 : "+f"(c[0]), "+f"(c[1]), "+f"(c[2]), "+f"(c[3])
                 : "r"(a[0]), "r"(a[1]), "r"(a[2]), "r"(a[3]), "r"(b[0]), "r"(b[1]));
}
__device__ __forceinline__ void split2h(float x, __half& hi, __half& lo) {
    hi = __float2half_rn(x);
    lo = __float2half_rn(x - __half2float(hi));
}
__device__ __forceinline__ __half2 mk2h(__half a, __half b) {
    __half2 r; r.x = a; r.y = b; return r;
}
__device__ __forceinline__ uint32_t packh(float a, float b) {
    __half2 t = __floats2half2_rn(a, b);
    return *reinterpret_cast<uint32_t*>(&t);
}

// ------------------------- fused prep kernel --------------------------------
__global__ void prep_all_r17(
    const float* __restrict__ q, const float* __restrict__ k, const float* __restrict__ v,
    __half* __restrict__ qih, __half* __restrict__ qil,
    __half* __restrict__ kih, __half* __restrict__ kil,
    __half* __restrict__ vih, __half* __restrict__ vil, size_t nMD,
    const float* __restrict__ Wq, __half* __restrict__ wqh, size_t nDD,
    const float* __restrict__ Wk, __half* __restrict__ wkh, size_t nDK,
    const float* __restrict__ Wv, __half* __restrict__ wvh,
    const float* __restrict__ Wo, __half* __restrict__ woh)
{
    const size_t total = nMD + 2 * nDD + 2 * nDK;
    for (size_t i = (size_t)blockIdx.x * blockDim.x + threadIdx.x; i < total;
         i += (size_t)gridDim.x * blockDim.x) {
        if (i < nMD) {
            __half h, l;
            split2h(q[i], h, l); qih[i] = h; qil[i] = l;
            split2h(k[i], h, l); kih[i] = h; kil[i] = l;
            split2h(v[i], h, l); vih[i] = h; vil[i] = l;
        } else {
            size_t j = i - nMD;
            if (j < nDD)                 wqh[j] = __float2half_rn(Wq[j]);
            else if (j < nDD + nDK)      wkh[j - nDD] = __float2half_rn(Wk[j - nDD]);
            else if (j < nDD + 2 * nDK)  wvh[j - nDD - nDK] = __float2half_rn(Wv[j - nDD - nDK]);
            else                         woh[j - nDD - 2 * nDK] = __float2half_rn(Wo[j - nDD - 2 * nDK]);
        }
    }
}

// --------------------------- fp16 2-pass GEMM body --------------------------
// C = (Ah + Al)[M][K] * Bh[K][N] + bias; A segments {hi,lo} over logical K=2048.
// mode: 0 = f32 out; 1 = Q (*0.125, split hi/lo); 2 = V (hi only); 3 = K (hi, transpose)
// 3-stage cp.async ring: load t+2 in flight while computing t.
#define GBM 128
#define GBN 128
#define GBK 32
#define ASTR 40
#define BSTR 136
#define NSTG 3

__device__ __forceinline__ void gemm2_body(
    const __half* Ahi, const __half* Alo, const __half* Bh,
    const float* bias, __half* Chi, __half* Clo, float* Cf, int N, int mode,
    __half (*As)[GBM * ASTR], __half (*Bs)[GBK * BSTR],
    int rowBase, int colBase)
{
    const int tid = threadIdx.x, lane = tid & 31, wid = tid >> 5;
    const int wm = wid >> 2, wn = wid & 3;

    float acc[4][4][4];
#pragma unroll
    for (int a = 0; a < 4; a++)
#pragma unroll
        for (int b = 0; b < 4; b++)
#pragma unroll
            for (int c = 0; c < 4; c++) acc[a][b][c] = 0.f;

    auto loadTiles = [&](int s, int t) {
        const int kt = t * GBK, seg = kt >> 11, koff = kt & 2047;
        const __half* Ab = seg ? Alo : Ahi;
#pragma unroll
        for (int h = 0; h < 2; h++) {
            int c = tid + h * 256;
            cp16(&As[s][(c >> 2) * ASTR + (c & 3) * 8],
                 &Ab[(size_t)(rowBase + (c >> 2)) * D_MODEL + koff + (c & 3) * 8]);
        }
#pragma unroll
        for (int h = 0; h < 2; h++) {
            int c = tid + h * 256;
            cp16(&Bs[s][(c >> 4) * BSTR + (c & 15) * 8],
                 &Bh[(size_t)(koff + (c >> 4)) * N + colBase + (c & 15) * 8]);
        }
    };

    const int niter = K2 / GBK;      // 128
    loadTiles(0, 0); cp_commit();
    loadTiles(1, 1); cp_commit();

    int cur = 0;
    for (int t = 0; t < niter; t++) {
        if (t + 2 < niter) cp_wait<1>();   // stage t done; t+1 may still fly
        else cp_wait<0>();                 // drain tail
        __syncthreads();                   // smem visibility + WAR for stage reuse
        if (t + 2 < niter) { loadTiles((cur + 2 >= NSTG) ? cur + 2 - NSTG : cur + 2, t + 2); cp_commit(); }

        const __half* Ab = As[cur];
        const __half* Bb = Bs[cur];
#pragma unroll
        for (int kk = 0; kk < GBK; kk += 16) {
            uint32_t af[4][4], bf[2][4];
#pragma unroll
            for (int mi = 0; mi < 4; mi++)
                ldmA(af[mi], sptr(&Ab[(wm * 64 + mi * 16 + (lane & 15)) * ASTR
                                      + kk + 8 * (lane >> 4)]));
#pragma unroll
            for (int j = 0; j < 2; j++)
                ldmBT(bf[j], sptr(&Bb[(kk + (lane & 15)) * BSTR
                                      + wn * 32 + j * 16 + 8 * (lane >> 4)]));
#pragma unroll
            for (int mi = 0; mi < 4; mi++)
#pragma unroll
                for (int nj = 0; nj < 4; nj++)
                    mma16816h(acc[mi][nj], af[mi], &bf[nj >> 1][(nj & 1) * 2]);
        }
        cur = (cur + 1 == NSTG) ? 0 : cur + 1;
    }

#pragma unroll
    for (int mi = 0; mi < 4; mi++) {
        int row0 = rowBase + wm * 64 + mi * 16 + (lane >> 2);
#pragma unroll
        for (int nj = 0; nj < 4; nj++) {
            int col = colBase + wn * 32 + nj * 8 + 2 * (lane & 3);
            float bx = bias[col], by = bias[col + 1];
            float v00 = acc[mi][nj][0] + bx, v01 = acc[mi][nj][1] + by;
            float v10 = acc[mi][nj][2] + bx, v11 = acc[mi][nj][3] + by;
            if (mode == 0) {
                *reinterpret_cast<float2*>(Cf + (size_t)row0 * N + col) = make_float2(v00, v01);
                *reinterpret_cast<float2*>(Cf + (size_t)(row0 + 8) * N + col) = make_float2(v10, v11);
            } else if (mode == 1) {
                v00 *= 0.125f; v01 *= 0.125f; v10 *= 0.125f; v11 *= 0.125f;
                __half h00, l00, h01, l01, h10, l10, h11, l11;
                split2h(v00, h00, l00); split2h(v01, h01, l01);
                split2h(v10, h10, l10); split2h(v11, h11, l11);
                *reinterpret_cast<__half2*>(Chi + (size_t)row0 * N + col) = mk2h(h00, h01);
                *reinterpret_cast<__half2*>(Clo + (size_t)row0 * N + col) = mk2h(l00, l01);
                *reinterpret_cast<__half2*>(Chi + (size_t)(row0 + 8) * N + col) = mk2h(h10, h11);
                *reinterpret_cast<__half2*>(Clo + (size_t)(row0 + 8) * N + col) = mk2h(l10, l11);
            } else if (mode == 3) {
                int b = row0 >> 11, t = row0 & 2047;
                int g = col >> 6,  d = col & 63;
                size_t base0 = ((size_t)(b * 8 + g) * 64 + d) * SEQ;
                size_t base1 = base0 + SEQ;
                Chi[base0 + t]     = __float2half_rn(v00);
                Chi[base1 + t]     = __float2half_rn(v01);
                Chi[base0 + t + 8] = __float2half_rn(v10);
                Chi[base1 + t + 8] = __float2half_rn(v11);
            } else {
                *reinterpret_cast<__half2*>(Chi + (size_t)row0 * N + col) =
                    mk2h(__float2half_rn(v00), __float2half_rn(v01));
                *reinterpret_cast<__half2*>(Chi + (size_t)(row0 + 8) * N + col) =
                    mk2h(__float2half_rn(v10), __float2half_rn(v11));
            }
        }
    }
}

// unified Q+K+V projection: 768 CTAs, linearized blockIdx.x
__global__ __launch_bounds__(256, 2) void proj_all_r17(
    const __half* __restrict__ qih, const __half* __restrict__ qil,
    const __half* __restrict__ wqh, const float* __restrict__ bq,
    __half* __restrict__ Qh, __half* __restrict__ Ql,
    const __half* __restrict__ kih, const __half* __restrict__ kil,
    const __half* __restrict__ wkh, const float* __restrict__ bk,
    __half* __restrict__ KhT,
    const __half* __restrict__ vih, const __half* __restrict__ vil,
    const __half* __restrict__ wvh, const float* __restrict__ bv,
    __half* __restrict__ Vh)
{
    __shared__ __half As[NSTG][GBM * ASTR];
    __shared__ __half Bs[NSTG][GBK * BSTR];
    const int bid = blockIdx.x;
    if (bid < 512) {
        gemm2_body(qih, qil, wqh, bq, Qh, Ql, nullptr, D_MODEL, 1, As, Bs,
                   (bid >> 4) * GBM, (bid & 15) * GBN);
    } else {
        const int b2 = bid - 512;
        const int z = b2 >> 7;
        const int r = (b2 & 127) >> 2, c = b2 & 3;
        if (z == 0)
            gemm2_body(kih, kil, wkh, bk, KhT, nullptr, nullptr, KV_DIM, 3, As, Bs,
                       r * GBM, c * GBN);
        else
            gemm2_body(vih, vil, wvh, bv, Vh, nullptr, nullptr, KV_DIM, 2, As, Bs,
                       r * GBM, c * GBN);
    }
}

// O projection
__global__ __launch_bounds__(256, 2) void gemm2_r17(
    const __half* __restrict__ Ahi, const __half* __restrict__ Alo,
    const __half* __restrict__ Bh,
    const float* __restrict__ bias, float* __restrict__ Cf, int N)
{
    __shared__ __half As[NSTG][GBM * ASTR];
    __shared__ __half Bs[NSTG][GBK * BSTR];
    gemm2_body(Ahi, Alo, Bh, bias, nullptr, nullptr, Cf, N, 0, As, Bs,
               blockIdx.y * GBM, blockIdx.x * GBN);
}

// ---------------- flash attention (validated: 2 heads / CTA, 2 CTA/SM) ------
#define FSTR 72

__global__ __launch_bounds__(256, 2) void gqa_flash_r17(
    const __half* __restrict__ Qh, const __half* __restrict__ Ql,
    const __half* __restrict__ KhT, const __half* __restrict__ Vh,
    __half* __restrict__ AOh, __half* __restrict__ AOl)
{
    extern __shared__ char smraw[];
    __half* Qhi = (__half*)smraw;                  // [128][FSTR]
    __half* Qlo = Qhi + 128 * FSTR;
    __half* Khs = Qlo + 128 * FSTR;                // [2][64][FSTR]
    __half* Vhs = Khs + 2 * 64 * FSTR;             // [2][64][FSTR]

    const int tid = threadIdx.x, lane = tid & 31, wid = tid >> 5;
    const int grp = lane >> 2, tq = lane & 3;
    const int qblk = blockIdx.x, hp = blockIdx.y, b = blockIdx.z;
    const int g = hp >> 1;
    const size_t bg = (size_t)(b * 8 + g);
    const int g64 = g * 64;

    auto loadKV = [&](int st, int jb) {
#pragma unroll
        for (int h = 0; h < 2; h++) {
            int c = tid + h * 256;
            int r = c >> 3, off8 = (c & 7) * 8;
            size_t ksrc = (bg * 64 + r) * (size_t)SEQ + jb * 64 + off8;
            size_t vsrc = ((size_t)(b * SEQ + jb * 64 + r)) * KV_DIM + g64 + off8;
            cp16(Khs + st * 64 * FSTR + r * FSTR + off8, KhT + ksrc);
            cp16(Vhs + st * 64 * FSTR + r * FSTR + off8, Vh + vsrc);
        }
    };

    loadKV(0, 0); cp_commit();
#pragma unroll
    for (int h = 0; h < 4; h++) {
        int c = tid + h * 256;
        int r = c >> 3, off8 = (c & 7) * 8;
        size_t src = ((size_t)(b * SEQ + qblk * 64 + (r & 63))) * D_MODEL
                   + (hp * 2 + (r >> 6)) * 64 + off8;
        cp16(Qhi + r * FSTR + off8, Qh + src);
        cp16(Qlo + r * FSTR + off8, Ql + src);
    }
    cp_commit();

    float m0 = -1e30f, m1 = -1e30f, l0 = 0.f, l1 = 0.f;
    float o[8][4];
#pragma unroll
    for (int i = 0; i < 8; i++)
#pragma unroll
        for (int j = 0; j < 4; j++) o[i][j] = 0.f;

    const uint32_t arow = (wid * 16 + (lane & 15)) * FSTR + 8 * (lane >> 4);
    const uint32_t brow = (lane & 15) * FSTR + 8 * (lane >> 4);

    for (int jb = 0; jb < SEQ / 64; jb++) {
        const int cur = jb & 1;
        cp_wait<0>();
        __syncthreads();
        if (jb + 1 < SEQ / 64) { loadKV(1 - cur, jb + 1); cp_commit(); }

        const __half* Kc = Khs + cur * 64 * FSTR;
        const __half* Vc = Vhs + cur * 64 * FSTR;

        // ---- S = (Qh + Ql) @ Kh^T (2-pass) ----
        float s[8][4];
#pragma unroll
        for (int i = 0; i < 8; i++)
#pragma unroll
            for (int j = 0; j < 4; j++) s[i][j] = 0.f;

#pragma unroll
        for (int p = 0; p < 2; p++) {
            const __half* Aseg = p ? Qlo : Qhi;
#pragma unroll
            for (int kk = 0; kk < 4; kk++) {
                uint32_t af[4], bf[4][4];
                ldmA(af, sptr(Aseg + kk * 16 + arow));
#pragma unroll
                for (int j = 0; j < 4; j++)
                    ldmBT(bf[j], sptr(Kc + kk * 16 * FSTR + j * 16 + brow));
#pragma unroll
                for (int nj = 0; nj < 8; nj++)
                    mma16816h(s[nj], af, &bf[nj >> 1][(nj & 1) * 2]);
            }
        }

        // ---- online softmax in registers ----
        float pm0 = -1e30f, pm1 = -1e30f;
#pragma unroll
        for (int nj = 0; nj < 8; nj++) {
            pm0 = fmaxf(pm0, fmaxf(s[nj][0], s[nj][1]));
            pm1 = fmaxf(pm1, fmaxf(s[nj][2], s[nj][3]));
        }
        pm0 = fmaxf(pm0, __shfl_xor_sync(~0u, pm0, 1));
        pm0 = fmaxf(pm0, __shfl_xor_sync(~0u, pm0, 2));
        pm1 = fmaxf(pm1, __shfl_xor_sync(~0u, pm1, 1));
        pm1 = fmaxf(pm1, __shfl_xor_sync(~0u, pm1, 2));
        float mn0 = fmaxf(m0, pm0), mn1 = fmaxf(m1, pm1);
        float corr0 = __expf(m0 - mn0), corr1 = __expf(m1 - mn1);
        m0 = mn0; m1 = mn1;

        float ls0 = 0.f, ls1 = 0.f;
        uint32_t pHi[4][4], pLo[4][4];
#pragma unroll
        for (int nj = 0; nj < 8; nj++) {
            float p0 = __expf(s[nj][0] - mn0);
            float p1 = __expf(s[nj][1] - mn0);
            float p2 = __expf(s[nj][2] - mn1);
            float p3 = __expf(s[nj][3] - mn1);
            ls0 += p0 + p1; ls1 += p2 + p3;
            const int kk = nj >> 1, hf = (nj & 1) * 2;
            uint32_t h01 = packh(p0, p1), h23 = packh(p2, p3);
            pHi[kk][hf]     = h01;
            pHi[kk][hf + 1] = h23;
            __half2 hh01 = *reinterpret_cast<__half2*>(&h01);
            __half2 hh23 = *reinterpret_cast<__half2*>(&h23);
            pLo[kk][hf]     = packh(p0 - __half2float(hh01.x),
                                    p1 - __half2float(hh01.y));
            pLo[kk][hf + 1] = packh(p2 - __half2float(hh23.x),
                                    p3 - __half2float(hh23.y));
        }
        ls0 += __shfl_xor_sync(~0u, ls0, 1); ls0 += __shfl_xor_sync(~0u, ls0, 2);
        ls1 += __shfl_xor_sync(~0u, ls1, 1); ls1 += __shfl_xor_sync(~0u, ls1, 2);
        l0 = l0 * corr0 + ls0;
        l1 = l1 * corr1 + ls1;
#pragma unroll
        for (int nj = 0; nj < 8; nj++) {
            o[nj][0] *= corr0; o[nj][1] *= corr0;
            o[nj][2] *= corr1; o[nj][3] *= corr1;
        }

        // ---- O += (Ph + Pl) @ Vh (2-pass, P in registers) ----
#pragma unroll
        for (int p = 0; p < 2; p++) {
            const uint32_t (*Pa)[4] = p ? pLo : pHi;
#pragma unroll
            for (int kk = 0; kk < 4; kk++) {
                uint32_t bf[4][4];
#pragma unroll
                for (int j = 0; j < 4; j++)
                    ldmBT(bf[j], sptr(Vc + kk * 16 * FSTR + j * 16 + brow));
#pragma unroll
                for (int nj = 0; nj < 8; nj++)
                    mma16816h(o[nj], Pa[kk], &bf[nj >> 1][(nj & 1) * 2]);
            }
        }
    }

    // ---- epilogue: normalize + split-write AO ----
    const int rowa = wid * 16 + grp;
    float il0 = 1.f / l0, il1 = 1.f / l1;
    int head = hp * 2 + (rowa >> 6);
    size_t m0r = (size_t)(b * SEQ + qblk * 64 + (rowa & 63));
#pragma unroll
    for (int nj = 0; nj < 8; nj++) {
        int col = head * 64 + nj * 8 + 2 * tq;
        float v00 = o[nj][0] * il0, v01 = o[nj][1] * il0;
        float v10 = o[nj][2] * il1, v11 = o[nj][3] * il1;
        __half h00, l00, h01, l01, h10, l10, h11, l11;
        split2h(v00, h00, l00); split2h(v01, h01, l01);
        split2h(v10, h10, l10); split2h(v11, h11, l11);
        *reinterpret_cast<__half2*>(AOh + m0r * D_MODEL + col) = mk2h(h00, h01);
        *reinterpret_cast<__half2*>(AOl + m0r * D_MODEL + col) = mk2h(l00, l01);
        *reinterpret_cast<__half2*>(AOh + (m0r + 8) * D_MODEL + col) = mk2h(h10, h11);
        *reinterpret_cast<__half2*>(AOl + (m0r + 8) * D_MODEL + col) = mk2h(l10, l11);
    }
}

// -----------------------------------------------------------------------------
extern "C" void kernel_launch(void* const* d_in, const int* in_sizes, int n_in,
                              void* d_out, int out_size)
{
    (void)in_sizes; (void)n_in; (void)out_size;
    const float* q  = (const float*)d_in[0];
    const float* k  = (const float*)d_in[1];
    const float* v  = (const float*)d_in[2];
    const float* Wq = (const float*)d_in[3];
    const float* bq = (const float*)d_in[4];
    const float* Wk = (const float*)d_in[5];
    const float* bk = (const float*)d_in[6];
    const float* Wv = (const float*)d_in[7];
    const float* bv = (const float*)d_in[8];
    const float* Wo = (const float*)d_in[9];
    const float* bo = (const float*)d_in[10];
    float* out = (float*)d_out;

    __half *qih,*qil,*kih,*kil,*vih,*vil;
    __half *wqh,*wkh,*wvh,*woh;
    __half *Qh,*Ql,*KhT,*Vh,*AOh,*AOl;
    cudaGetSymbolAddress((void**)&qih, s_qih); cudaGetSymbolAddress((void**)&qil, s_qil);
    cudaGetSymbolAddress((void**)&kih, s_kih); cudaGetSymbolAddress((void**)&kil, s_kil);
    cudaGetSymbolAddress((void**)&vih, s_vih); cudaGetSymbolAddress((void**)&vil, s_vil);
    cudaGetSymbolAddress((void**)&wqh, s_wqh); cudaGetSymbolAddress((void**)&wkh, s_wkh);
    cudaGetSymbolAddress((void**)&wvh, s_wvh); cudaGetSymbolAddress((void**)&woh, s_woh);
    cudaGetSymbolAddress((void**)&Qh,  g_Qh);  cudaGetSymbolAddress((void**)&Ql,  g_Ql);
    cudaGetSymbolAddress((void**)&KhT, g_KhT); cudaGetSymbolAddress((void**)&Vh,  g_Vh);
    cudaGetSymbolAddress((void**)&AOh, g_AOh); cudaGetSymbolAddress((void**)&AOl, g_AOl);

    const size_t flash_smem =
        (2 * 128 * FSTR + 2 * 2 * 64 * FSTR) * sizeof(__half);   // 73728
    cudaFuncSetAttribute(gqa_flash_r17, cudaFuncAttributeMaxDynamicSharedMemorySize,
                         (int)flash_smem);

    const size_t nMD = (size_t)M_TOT * D_MODEL;
    const size_t nDD = (size_t)D_MODEL * D_MODEL;
    const size_t nDK = (size_t)D_MODEL * KV_DIM;

    // fused prep: one launch for all splits + casts
    prep_all_r17<<<2048, 256>>>(q, k, v, qih, qil, kih, kil, vih, vil, nMD,
                                Wq, wqh, nDD, Wk, wkh, nDK, Wv, wvh, Wo, woh);

    // unified Q+K+V projections (768 CTAs, one tail, 3-stage pipeline)
    proj_all_r17<<<768, 256>>>(
        qih, qil, wqh, bq, Qh, Ql,
        kih, kil, wkh, bk, KhT,
        vih, vil, wvh, bv, Vh);

    // attention (2 heads / CTA, 256 threads, 2 CTA/SM — validated config)
    gqa_flash_r17<<<dim3(SEQ / 64, NUM_HEADS / 2, BATCH), 256, flash_smem>>>(
        Qh, Ql, KhT, Vh, AOh, AOl);

    // output projection (3-stage pipeline)
    gemm2_r17<<<dim3(D_MODEL / GBN, M_TOT / GBM), 256>>>(AOh, AOl, woh, bo, out, D_MODEL);
}